// round 14
// baseline (speedup 1.0000x reference)
#include <cuda_runtime.h>

// AverageSpanExtractor: out[b,n,:] = mean(seq[b, start:end, :]) * mask[b,n]
// seq: [B,S,D] f32; spans: [B,N,2] i32; mask: [B,N] i32; out: [B,N,D] f32.
//
// Placement-locality scheme. Classic CTA placement is LUT[bid % 148], so all
// linear bids congruent mod 148 run on the SAME SM. A scheduling pass bins
// each span by its sequence position into group g (0..147) and slot i; the
// reduce kernel (grid 148 x 96, linear bid = g + 148*i) therefore executes
// all spans of a group on one SM. Their rows live in a narrow window that
// stays L1-resident (L1 persists across CTA retirement within a launch), so
// each unique row is pulled from L2 about once per SM: gather L2 traffic
// drops ~172MB -> ~39MB, below the LTS cap that pinned flat schemes at 15us.
// Reduce body = the proven R3 per-span kernel, unchanged.

#define MAX_W    20
#define DIM      512
#define D4       (DIM / 4)
#define NSM      148
#define SLOT_CAP 96          // Poisson(55.4) max over 148 groups; >96 ~ 1e-6

__device__ int  g_count[NSM];
__device__ int4 g_slots[NSM * SLOT_CAP];   // (span_id, abs_cell, width, mask)

__global__ void zero_kernel()
{
    if (threadIdx.x < NSM) g_count[threadIdx.x] = 0;
}

__global__ void assign_kernel(const int* __restrict__ spans,
                              const int* __restrict__ mask,
                              const float* __restrict__ seq,
                              float* __restrict__ out,
                              int S, int N, int total_cells, int total)
{
    const int i = blockIdx.x * blockDim.x + threadIdx.x;
    if (i >= total) return;

    const int2 se = ((const int2*)spans)[i];
    const int b = i / N;
    const int cell = b * S + se.x;               // absolute (b,row) cell
    int w = se.y - se.x;
    w = (w < MAX_W) ? w : MAX_W;                 // reference's static clamp
    w = (w > 0) ? w : 1;

    const int g = (int)(((long long)cell * NSM) / total_cells);
    const int slot = atomicAdd(&g_count[g], 1);
    if (slot < SLOT_CAP) {
        g_slots[g * SLOT_CAP + slot] = make_int4(i, cell, w, mask[i]);
    } else {
        // statistically unreachable overflow: reduce directly (correct, slow)
        const float scale = (float)mask[i] / (float)w;
        const float* src = seq + (long long)cell * DIM;
        float* o = out + (long long)i * DIM;
        for (int d = 0; d < DIM; ++d) {
            float a = 0.f;
            for (int r = 0; r < w; ++r) a += src[r * DIM + d];
            o[d] = a * scale;
        }
    }
}

__global__ __launch_bounds__(128, 12)
void reduce_kernel(const float* __restrict__ seq,
                   float* __restrict__ out)
{
    const int g    = blockIdx.x;                 // group -> fixed SM (bid%148)
    const int slot = blockIdx.y;
    if (slot >= min(g_count[g], SLOT_CAP)) return;

    const int4 e = g_slots[g * SLOT_CAP + slot]; // (span_id, cell, w, mask)
    const int t = threadIdx.x;                   // owns float4 column t

    const float4* p = (const float4*)seq + (long long)e.y * D4 + t;
    float4 acc = make_float4(0.f, 0.f, 0.f, 0.f);

    #pragma unroll 4
    for (int r = 0; r < e.z; ++r) {
        float4 v = *p;
        p += D4;
        acc.x += v.x; acc.y += v.y; acc.z += v.z; acc.w += v.w;
    }

    const float s = (float)e.w / (float)e.z;
    acc.x *= s; acc.y *= s; acc.z *= s; acc.w *= s;

    float4* o = (float4*)out + (long long)e.x * D4;
    o[t] = acc;
}

extern "C" void kernel_launch(void* const* d_in, const int* in_sizes, int n_in,
                              void* d_out, int out_size)
{
    const float* seq  = (const float*)d_in[0];
    const int* spans  = (const int*)d_in[1];
    const int* mask   = (const int*)d_in[2];
    float* out        = (float*)d_out;

    const int S = 2048;
    const int B = in_sizes[0] / (S * DIM);       // 8
    const int N = in_sizes[2] / B;               // 1024
    const int total = B * N;                     // 8192
    const int total_cells = B * S;               // 16384

    zero_kernel<<<1, NSM>>>();
    assign_kernel<<<(total + 255) / 256, 256>>>(spans, mask, seq, out,
                                                S, N, total_cells, total);
    dim3 grid(NSM, SLOT_CAP);
    reduce_kernel<<<grid, 128>>>(seq, out);
}

// round 15
// speedup vs baseline: 1.0413x; 1.0413x over previous
#include <cuda_runtime.h>
#include <cstdint>

// AverageSpanExtractor: out[b,n,:] = mean(seq[b, start:end, :]) * mask[b,n]
// seq: [B,S,D] f32; spans: [B,N,2] i32; mask: [B,N] i32; out: [B,N,D] f32.
//
// Bulk-DMA bucket kernel. Evidence from R3..R14: every LDG scheme is capped
// by per-SM outstanding-load tracking (~2KB in flight); cp.async per-16B
// escaped that but died on LDGSTS issue cost. cp.async.bulk moves a whole
// 52-row slice (104KB) with ONE instruction through the DMA engine.
// Jobs = (batch, 32-row bucket) -> 512 jobs; slice covers bucket+20 margin,
// so every span starting in the bucket is contained. Unique-slice DMA
// traffic = 53MB (vs 172MB gather), reduce runs from smem (36TB/s path),
// double-buffered so job j+1's DMA overlaps job j's reduce.

#define MAX_W    20
#define DIM      512
#define D4       128
#define S_CONST  2048
#define BUCKET   32
#define NB       64                      // buckets per batch (S/BUCKET)
#define SLICE    (BUCKET + MAX_W)        // 52 rows
#define SLICE_BYTES (SLICE * DIM * 4)    // 106496
#define THREADS  1024
#define LIST_CAP 96

__device__ __forceinline__ uint32_t smem_u32(const void* p) {
    return (uint32_t)__cvta_generic_to_shared(p);
}

__global__ __launch_bounds__(THREADS, 1)
void avg_span_kernel(const float* __restrict__ seq,
                     const int* __restrict__ spans,
                     const int* __restrict__ mask,
                     float* __restrict__ out,
                     int S, int N, int jobs)
{
    extern __shared__ __align__(16) char sm[];
    float* buf  = (float*)sm;                                   // 2 x SLICE x DIM
    int4*  list = (int4*)(sm + 2 * SLICE_BYTES);                // 2 x LIST_CAP
    int*   cnt  = (int*)(list + 2 * LIST_CAP);                  // cnt[2]
    unsigned long long* mbar = (unsigned long long*)(cnt + 4);  // mbar[2]

    const int t = threadIdx.x;

    // ---- init ----
    if (t == 0) {
        cnt[0] = 0; cnt[1] = 0;
        asm volatile("mbarrier.init.shared.b64 [%0], 1;" :: "r"(smem_u32(&mbar[0])) : "memory");
        asm volatile("mbarrier.init.shared.b64 [%0], 1;" :: "r"(smem_u32(&mbar[1])) : "memory");
    }
    __syncthreads();

    int job = blockIdx.x;
    if (job >= jobs) return;

    auto dma = [&](int j, int st) {      // t==0 only
        const int bk = j & (NB - 1), b = j >> 6;
        const int row0 = bk * BUCKET;
        const int nrows = min(SLICE, S - row0);
        const uint32_t bytes = (uint32_t)nrows * DIM * 4;
        const uint32_t mb = smem_u32(&mbar[st]);
        asm volatile("fence.proxy.async.shared::cta;" ::: "memory");
        asm volatile("mbarrier.arrive.expect_tx.shared.b64 _, [%0], %1;"
                     :: "r"(mb), "r"(bytes) : "memory");
        asm volatile("cp.async.bulk.shared::cluster.global.mbarrier::complete_tx::bytes"
                     " [%0], [%1], %2, [%3];"
                     :: "r"(smem_u32(buf) + (uint32_t)st * SLICE_BYTES),
                        "l"(seq + ((long long)b * S + row0) * DIM),
                        "r"(bytes), "r"(mb) : "memory");
    };

    auto wait = [&](int st, int phase) {
        const uint32_t mb = smem_u32(&mbar[st]);
        uint32_t done;
        asm volatile("{\n\t.reg .pred p;\n\t"
                     "mbarrier.try_wait.parity.acquire.cta.shared::cta.b64 p, [%1], %2;\n\t"
                     "selp.b32 %0, 1, 0, p;\n\t}"
                     : "=r"(done) : "r"(mb), "r"((uint32_t)phase) : "memory");
        while (!done) {
            asm volatile("{\n\t.reg .pred p;\n\t"
                         "mbarrier.try_wait.parity.acquire.cta.shared::cta.b64 p, [%1], %2, 0x989680;\n\t"
                         "selp.b32 %0, 1, 0, p;\n\t}"
                         : "=r"(done) : "r"(mb), "r"((uint32_t)phase) : "memory");
        }
    };

    auto filter = [&](int j, int st) {
        const int bk = j & (NB - 1), b = j >> 6;
        const int row0 = bk * BUCKET;
        const int2* sp2 = (const int2*)spans + b * N;
        for (int n = t; n < N; n += THREADS) {
            const int2 se = sp2[n];
            if (se.x >= row0 && se.x < row0 + BUCKET) {
                int w = se.y - se.x;
                w = (w < MAX_W) ? w : MAX_W;         // reference's static clamp
                w = (w > 0) ? w : 1;
                const int i = atomicAdd(&cnt[st], 1);
                if (i < LIST_CAP) {
                    list[st * LIST_CAP + i] = make_int4(n, se.x - row0, w, mask[b * N + n]);
                } else {  // statistically unreachable: direct global reduce
                    const float scale = (float)mask[b * N + n] / (float)w;
                    const float* g = seq + ((long long)b * S + se.x) * DIM;
                    float* o = out + ((long long)(b * N + n)) * DIM;
                    for (int d = 0; d < DIM; ++d) {
                        float a = 0.f;
                        for (int r = 0; r < w; ++r) a += g[r * DIM + d];
                        o[d] = a * scale;
                    }
                }
            }
        }
    };

    auto reduce = [&](int j, int st) {
        const int b = j >> 6;
        const int c = min(cnt[st], LIST_CAP);
        const int ntasks = 2 * c;                    // half-span tasks
        const float4* bb = (const float4*)(sm + st * SLICE_BYTES);
        const int wid = t >> 5, lane = t & 31;
        for (int task = wid; task < ntasks; task += (THREADS / 32)) {
            const int4 e = list[st * LIST_CAP + (task >> 1)];  // (n, ls, w, m)
            const int half = task & 1;
            const float4* p = bb + e.y * D4 + half * 64 + lane;

            float4 a0 = make_float4(0.f, 0.f, 0.f, 0.f);
            float4 a1 = a0;
            #pragma unroll 2
            for (int r = 0; r < e.z; ++r) {
                float4 v0 = p[0], v1 = p[32];
                p += D4;
                a0.x += v0.x; a0.y += v0.y; a0.z += v0.z; a0.w += v0.w;
                a1.x += v1.x; a1.y += v1.y; a1.z += v1.z; a1.w += v1.w;
            }
            const float s = (float)e.w / (float)e.z;
            a0.x *= s; a0.y *= s; a0.z *= s; a0.w *= s;
            a1.x *= s; a1.y *= s; a1.z *= s; a1.w *= s;

            float4* o = (float4*)out + ((long long)b * N + e.x) * D4 + half * 64 + lane;
            o[0] = a0; o[32] = a1;
        }
    };

    // ---- prologue: start DMA + filter for first job ----
    if (t == 0) dma(job, 0);
    filter(job, 0);
    __syncthreads();                 // list[0] complete

    int st = 0;
    int ph[2] = {0, 0};
    while (true) {
        const int next = job + gridDim.x;
        const bool have = (next < jobs);
        if (have) {
            if (t == 0) dma(next, st ^ 1);
            filter(next, st ^ 1);    // cnt[st^1] is 0 (reset after its reduce)
            __syncthreads();         // list[st^1] complete
        }

        wait(st, ph[st]); ph[st] ^= 1;
        reduce(job, st);

        if (!have) break;
        __syncthreads();             // reduce done before cnt[st] reset
        if (t == 0) cnt[st] = 0;
        __syncthreads();             // reset visible before buf[st]/cnt[st] reuse

        job = next;
        st ^= 1;
    }
}

extern "C" void kernel_launch(void* const* d_in, const int* in_sizes, int n_in,
                              void* d_out, int out_size)
{
    const float* seq  = (const float*)d_in[0];
    const int* spans  = (const int*)d_in[1];
    const int* mask   = (const int*)d_in[2];
    float* out        = (float*)d_out;

    const int S = S_CONST;
    const int B = in_sizes[0] / (S * DIM);       // 8
    const int N = in_sizes[2] / B;               // 1024
    const int jobs = NB * B;                     // 512

    const int smem_bytes = 2 * SLICE_BYTES + 2 * LIST_CAP * 16 + 64;
    static bool attr_set = false;
    if (!attr_set) {
        cudaFuncSetAttribute(avg_span_kernel,
                             cudaFuncAttributeMaxDynamicSharedMemorySize, smem_bytes);
        attr_set = true;
    }

    avg_span_kernel<<<148, THREADS, smem_bytes>>>(seq, spans, mask, out, S, N, jobs);
}

// round 16
// speedup vs baseline: 1.0933x; 1.0500x over previous
#include <cuda_runtime.h>

// AverageSpanExtractor: out[b,n,:] = mean(seq[b, start:end, :]) * mask[b,n]
// seq: [B,S,D] f32; spans: [B,N,2] i32; mask: [B,N] i32; out: [B,N,D] f32.
//
// L1-dedup bucket kernel. CTA per (batch, 32-row bucket): all its spans'
// rows live in a 52-row / 104KB window. Occupancy is capped at 2 CTAs/SM by
// an 80KB dummy dynamic-smem request, so the two resident windows (208KB)
// fit in the 228KB L1D -> repeated row reads hit L1; L2 sees first-touches
// only (~75MB total vs the 188MB that pinned flat schemes at the LTS cap).
// Execution = R3's proven LDG/unroll body, parallel half-span tasks, one
// barrier per CTA.

#define MAX_W    20
#define DIM      512
#define D4       128
#define BUCKET   32
#define LIST_CAP 96          // Poisson(16) spans/bucket; 96 unreachable
#define THREADS  512

__global__ __launch_bounds__(THREADS, 2)
void avg_span_kernel(const float* __restrict__ seq,
                     const int* __restrict__ spans,
                     const int* __restrict__ mask,
                     float* __restrict__ out,
                     int S, int N)
{
    extern __shared__ char smem_raw[];           // 80KB requested (occ cap)
    int4* list = (int4*)smem_raw;                // (n, start, width, mask)
    int*  cntp = (int*)(list + LIST_CAP);

    const int bucket = blockIdx.x;
    const int b      = blockIdx.y;
    const int t      = threadIdx.x;

    if (t == 0) *cntp = 0;
    __syncthreads();

    const int lo = bucket * BUCKET;
    const int hi = lo + BUCKET;

    // ---- filter: spans of batch b starting in [lo, hi) ----
    const int2* sp2 = (const int2*)spans + b * N;
    for (int n = t; n < N; n += THREADS) {
        const int2 se = sp2[n];
        if (se.x >= lo && se.x < hi) {
            int w = se.y - se.x;
            w = (w < MAX_W) ? w : MAX_W;         // reference's static clamp
            w = (w > 0) ? w : 1;
            const int i = atomicAdd(cntp, 1);
            if (i < LIST_CAP) {
                list[i] = make_int4(n, se.x, w, mask[b * N + n]);
            } else {
                // statistically unreachable overflow: direct reduce (correct)
                const float scale = (float)mask[b * N + n] / (float)w;
                const float* g = seq + ((long long)b * S + se.x) * DIM;
                float* o = out + ((long long)(b * N + n)) * DIM;
                for (int d = 0; d < DIM; ++d) {
                    float a = 0.f;
                    for (int r = 0; r < w; ++r) a += g[r * DIM + d];
                    o[d] = a * scale;
                }
            }
        }
    }
    __syncthreads();

    const int c = min(*cntp, LIST_CAP);
    const int ntasks = 2 * c;                    // half-span tasks, 64 f4 cols
    const int wid  = t >> 5;                     // 0..15
    const int lane = t & 31;

    const float4* __restrict__ seqb = (const float4*)seq + (long long)b * S * D4;
    float4* __restrict__ outb = (float4*)out + (long long)b * N * D4;

    // ---- parallel half-span reduction; window rows L1-resident ----
    for (int task = wid; task < ntasks; task += (THREADS / 32)) {
        const int4 e = list[task >> 1];          // (n, start, w, mask)
        const int half = task & 1;

        const float4* p = seqb + e.y * D4 + half * 64 + lane;

        float4 a0 = make_float4(0.f, 0.f, 0.f, 0.f);
        float4 a1 = a0;

        #pragma unroll 4
        for (int r = 0; r < e.z; ++r) {
            float4 v0 = p[0], v1 = p[32];
            p += D4;
            a0.x += v0.x; a0.y += v0.y; a0.z += v0.z; a0.w += v0.w;
            a1.x += v1.x; a1.y += v1.y; a1.z += v1.z; a1.w += v1.w;
        }

        const float s = (float)e.w / (float)e.z;
        a0.x *= s; a0.y *= s; a0.z *= s; a0.w *= s;
        a1.x *= s; a1.y *= s; a1.z *= s; a1.w *= s;

        float4* o = outb + e.x * D4 + half * 64 + lane;
        o[0] = a0; o[32] = a1;
    }
}

extern "C" void kernel_launch(void* const* d_in, const int* in_sizes, int n_in,
                              void* d_out, int out_size)
{
    const float* seq  = (const float*)d_in[0];
    const int* spans  = (const int*)d_in[1];
    const int* mask   = (const int*)d_in[2];
    float* out        = (float*)d_out;

    const int S = 2048;
    const int B = in_sizes[0] / (S * DIM);       // 8
    const int N = in_sizes[2] / B;               // 1024

    // 80KB dummy smem: caps residency at 2 CTAs/SM so both CTAs' gather
    // windows (2 x 104KB) stay L1-resident.
    const int smem_bytes = 80 * 1024;
    static bool attr_set = false;
    if (!attr_set) {
        cudaFuncSetAttribute(avg_span_kernel,
                             cudaFuncAttributeMaxDynamicSharedMemorySize, smem_bytes);
        attr_set = true;
    }

    dim3 grid(S / BUCKET, B);                    // (64, 8) = 512 CTAs
    avg_span_kernel<<<grid, THREADS, smem_bytes>>>(seq, spans, mask, out, S, N);
}